// round 6
// baseline (speedup 1.0000x reference)
#include <cuda_runtime.h>
#include <cstddef>

#define NROWS 16384
#define INDIM 768
#define CDIM  256
#define KCODES 4096

// ---- device scratch (static: allowed; no runtime allocation) ----
__device__ float g_zqsum[NROWS * CDIM];      // running zq sum -> decoder input
__device__ float g_esq[4][KCODES];           // ||E_k||^2 per codebook
__device__ float g_ze2[NROWS];               // ||ze||^2 for current stage
__device__ int   g_nn[4][NROWS];             // argmin indices per stage

// ---- packed f32x2 helpers: each lane rounds .rn independently, so each
// output keeps its single ascending-k fma chain -> bit-exact vs scalar ----
__device__ __forceinline__ void fma2(unsigned long long& d,
                                     unsigned long long a,
                                     unsigned long long b)
{
    asm("fma.rn.f32x2 %0, %1, %2, %0;" : "+l"(d) : "l"(a), "l"(b));
}
__device__ __forceinline__ unsigned long long dup2(float x)
{
    unsigned long long r;
    asm("mov.b64 %0, {%1, %1};" : "=l"(r) : "f"(x));
    return r;
}
__device__ __forceinline__ float2 unpk2(unsigned long long v)
{
    float2 r;
    asm("mov.b64 {%0, %1}, %2;" : "=f"(r.x), "=f"(r.y) : "l"(v));
    return r;
}

// ============================================================================
// fp32 SGEMM with bias via packed f32x2: C = A @ B + bias.
// 128x128 tile, 8x8 per thread (4 f32x2 column-pairs).
// ============================================================================
__global__ __launch_bounds__(256) void sgemm_bias_kernel(
    const float* __restrict__ A, const float* __restrict__ B,
    const float* __restrict__ bias, float* __restrict__ C,
    int M, int Kd, int Nn)
{
    __shared__ __align__(16) float As[32][132];  // [kk][mm]
    __shared__ __align__(16) float Bs[32][132];  // [kk][nn]

    const int tid = threadIdx.x;
    const int tx = tid & 15;
    const int ty = tid >> 4;
    const int m0 = blockIdx.y * 128;
    const int n0 = blockIdx.x * 128;

    unsigned long long acc[8][4];
#pragma unroll
    for (int i = 0; i < 8; i++)
#pragma unroll
        for (int j = 0; j < 4; j++) acc[i][j] = 0ull;

    for (int k0 = 0; k0 < Kd; k0 += 32) {
#pragma unroll
        for (int i = 0; i < 16; i++) {
            int idx = tid + i * 256;
            int mm = idx >> 5, kk = idx & 31;
            As[kk][mm] = A[(size_t)(m0 + mm) * Kd + (k0 + kk)];
        }
#pragma unroll
        for (int i = 0; i < 16; i++) {
            int idx = tid + i * 256;
            int kk = idx >> 7, nn = idx & 127;
            Bs[kk][nn] = B[(size_t)(k0 + kk) * Nn + (n0 + nn)];
        }
        __syncthreads();

#pragma unroll
        for (int kk = 0; kk < 32; kk++) {
            float4 a0 = *(const float4*)&As[kk][ty * 4];
            float4 a1 = *(const float4*)&As[kk][64 + ty * 4];
            unsigned long long aa[8] = {dup2(a0.x), dup2(a0.y), dup2(a0.z), dup2(a0.w),
                                        dup2(a1.x), dup2(a1.y), dup2(a1.z), dup2(a1.w)};
            ulonglong2 b0 = *(const ulonglong2*)&Bs[kk][tx * 4];
            ulonglong2 b1 = *(const ulonglong2*)&Bs[kk][64 + tx * 4];
            unsigned long long bb[4] = {b0.x, b0.y, b1.x, b1.y};
#pragma unroll
            for (int i = 0; i < 8; i++)
#pragma unroll
                for (int j = 0; j < 4; j++)
                    fma2(acc[i][j], aa[i], bb[j]);
        }
        __syncthreads();
    }

#pragma unroll
    for (int i = 0; i < 8; i++) {
        int row = m0 + ((i < 4) ? (ty * 4 + i) : (64 + ty * 4 + (i - 4)));
#pragma unroll
        for (int jh = 0; jh < 2; jh++) {
            int col = n0 + (jh ? (64 + tx * 4) : (tx * 4));
            float2 p0 = unpk2(acc[i][jh * 2 + 0]);
            float2 p1 = unpk2(acc[i][jh * 2 + 1]);
            float4 v;
            v.x = __fadd_rn(p0.x, bias[col + 0]);
            v.y = __fadd_rn(p0.y, bias[col + 1]);
            v.z = __fadd_rn(p1.x, bias[col + 2]);
            v.w = __fadd_rn(p1.y, bias[col + 3]);
            *(float4*)&C[(size_t)row * Nn + col] = v;
        }
    }
}

// ============================================================================
// ||E_k||^2 for ALL FOUR codebooks in one launch (XLA rounding order).
// ============================================================================
__global__ void esq4_kernel(const float* __restrict__ E0,
                            const float* __restrict__ E1,
                            const float* __restrict__ E2,
                            const float* __restrict__ E3)
{
    int gid = blockIdx.x * 256 + threadIdx.x;
    int stage = gid >> 12;
    int row = gid & (KCODES - 1);
    const float* E = (stage == 0) ? E0 : (stage == 1) ? E1 : (stage == 2) ? E2 : E3;
    const float* e = E + (size_t)row * CDIM;
    float s = 0.f;
#pragma unroll 8
    for (int c = 0; c < CDIM; c++) {
        float v = e[c];
        s = __fadd_rn(s, __fmul_rn(v, v));
    }
    g_esq[stage][row] = s;
}

// ============================================================================
// ||ze||^2 per row (stage 0 only; later stages fused into gather).
// ============================================================================
__global__ void rownorm_kernel(const float* __restrict__ ze)
{
    int row = blockIdx.x * 256 + threadIdx.x;
    if (row >= NROWS) return;
    const float* p = ze + (size_t)row * CDIM;
    float s = 0.f;
#pragma unroll 8
    for (int c = 0; c < CDIM; c++) {
        float v = __ldg(p + c);
        s = __fadd_rn(s, __fmul_rn(v, v));
    }
    g_ze2[row] = s;
}

// ============================================================================
// Fused score-GEMM + argmin, packed f32x2.
// BM=64 rows (grid 256, 2 CTAs/SM -> 4 warps/SMSP), BN=128 codes/chunk,
// BK=32, 256 threads, 4 rows x 8 cols per thread.
// Persistent ze tile in smem (filled once); double-buffered E tile with
// register-staged prefetch; STS hoisted to mid-chunk so the barrier drains
// no stores. d_k = fl( fl( Z - fl(2*s_k) ) + esq_k ); single fma chain per
// score; tie-break lowest index.
// Dynamic smem: As 256x68 (persistent) | Bs 2 x 32x132  = 103,424 B.
// ============================================================================
#define ASTRIDE 68
#define BSTRIDE 132
#define VQ_SMEM ((256 * ASTRIDE + 2 * 32 * BSTRIDE) * 4)

__global__ __launch_bounds__(256, 2) void vq_argmin_kernel(
    const float* __restrict__ ze,   // NROWS x CDIM
    const float* __restrict__ E,    // KCODES x CDIM
    int stage)
{
    extern __shared__ __align__(16) float sm[];
    float* As = sm;                         // [256 c][ASTRIDE]  persistent
    float* Bs = sm + 256 * ASTRIDE;         // [2][32 kk][BSTRIDE]

    const int tid = threadIdx.x;
    const int tx = tid & 15;
    const int ty = tid >> 4;                // 0..15 -> rows ty*4+{0..3}
    const int m0 = blockIdx.x * 64;
    const float* __restrict__ esq = g_esq[stage];

    // ---- one-time fill of the ze tile (64 rows x 256 c), coalesced LDG ----
#pragma unroll 8
    for (int i = 0; i < 64; i++) {
        As[tid * ASTRIDE + i] = ze[(size_t)(m0 + i) * CDIM + tid];
    }
    // ---- fill Bs buffer 0 with chunk t=0 (cb=0, c0=0) ----
#pragma unroll
    for (int i = 0; i < 16; i++) {
        int idx = tid + i * 256;
        int code = idx >> 5, kk = idx & 31;
        Bs[kk * BSTRIDE + code] = E[(size_t)code * CDIM + kk];
    }
    __syncthreads();

    float zrow[4];
#pragma unroll
    for (int i = 0; i < 4; i++) zrow[i] = g_ze2[m0 + ty * 4 + i];

    float bestv[4];
    int   besti[4];
#pragma unroll
    for (int i = 0; i < 4; i++) { bestv[i] = 3.4e38f; besti[i] = 0; }

    unsigned long long acc[4][4];
    float stg[16];

    // 256 chunks: t -> cb = (t>>3)*128, c0 = (t&7)*32
    for (int t = 0; t < 256; t++) {
        const int p = t & 1;
        const int cb = (t >> 3) * 128;
        const int c0 = (t & 7) * 32;
        const bool has_next = (t < 255);

        // prefetch next chunk's E tile into registers
        if (has_next) {
            const int t1 = t + 1;
            const int cb1 = (t1 >> 3) * 128;
            const int c01 = (t1 & 7) * 32;
#pragma unroll
            for (int i = 0; i < 16; i++) {
                int idx = tid + i * 256;
                int code = idx >> 5, kk = idx & 31;
                stg[i] = E[(size_t)(cb1 + code) * CDIM + (c01 + kk)];
            }
        }

        if ((t & 7) == 0) {
#pragma unroll
            for (int i = 0; i < 4; i++)
#pragma unroll
                for (int j = 0; j < 4; j++) acc[i][j] = 0ull;
        }

        const float* Bp = Bs + p * (32 * BSTRIDE);

        // ---- first half: kk 0..15 ----
#pragma unroll
        for (int kk = 0; kk < 16; kk++) {
            const float* ar = As + (c0 + kk) * ASTRIDE;
            const float* br = Bp + kk * BSTRIDE;
            float4 a0 = *(const float4*)&ar[ty * 4];
            unsigned long long aa[4] = {dup2(a0.x), dup2(a0.y), dup2(a0.z), dup2(a0.w)};
            ulonglong2 b0 = *(const ulonglong2*)&br[tx * 4];
            ulonglong2 b1 = *(const ulonglong2*)&br[64 + tx * 4];
            unsigned long long bb[4] = {b0.x, b0.y, b1.x, b1.y};
#pragma unroll
            for (int i = 0; i < 4; i++)
#pragma unroll
                for (int j = 0; j < 4; j++)
                    fma2(acc[i][j], aa[i], bb[j]);
        }

        // ---- mid-chunk STS: stores complete during the second half, so the
        // end-of-chunk barrier has no STS left to drain ----
        if (has_next) {
            float* Bn = Bs + (p ^ 1) * (32 * BSTRIDE);
#pragma unroll
            for (int i = 0; i < 16; i++) {
                int idx = tid + i * 256;
                int code = idx >> 5, kk = idx & 31;
                Bn[kk * BSTRIDE + code] = stg[i];
            }
        }

        // ---- second half: kk 16..31 ----
#pragma unroll
        for (int kk = 16; kk < 32; kk++) {
            const float* ar = As + (c0 + kk) * ASTRIDE;
            const float* br = Bp + kk * BSTRIDE;
            float4 a0 = *(const float4*)&ar[ty * 4];
            unsigned long long aa[4] = {dup2(a0.x), dup2(a0.y), dup2(a0.z), dup2(a0.w)};
            ulonglong2 b0 = *(const ulonglong2*)&br[tx * 4];
            ulonglong2 b1 = *(const ulonglong2*)&br[64 + tx * 4];
            unsigned long long bb[4] = {b0.x, b0.y, b1.x, b1.y};
#pragma unroll
            for (int i = 0; i < 4; i++)
#pragma unroll
                for (int j = 0; j < 4; j++)
                    fma2(acc[i][j], aa[i], bb[j]);
        }

        // end of a cb group: argmin update  d = fl( fl(Z - fl(2*s)) + esq )
        if ((t & 7) == 7) {
#pragma unroll
            for (int jh = 0; jh < 2; jh++) {
#pragma unroll
                for (int h = 0; h < 2; h++) {
                    int j2 = jh * 2 + h;
                    int col = cb + jh * 64 + tx * 4 + h * 2;
                    float eq0 = esq[col];
                    float eq1 = esq[col + 1];
#pragma unroll
                    for (int i = 0; i < 4; i++) {
                        float2 pv = unpk2(acc[i][j2]);
                        float t0 = __fmul_rn(2.0f, pv.x);
                        float v0 = __fadd_rn(__fadd_rn(zrow[i], -t0), eq0);
                        if (v0 < bestv[i]) { bestv[i] = v0; besti[i] = col; }
                        float t1v = __fmul_rn(2.0f, pv.y);
                        float v1 = __fadd_rn(__fadd_rn(zrow[i], -t1v), eq1);
                        if (v1 < bestv[i]) { bestv[i] = v1; besti[i] = col + 1; }
                    }
                }
            }
        }
        __syncthreads();
    }

    // cross-thread reduction over the 16 tx lanes sharing each row
    float* rv = sm;                  // 64*16 floats
    int*   ri = (int*)(sm + 1024);   // 64*16 ints
#pragma unroll
    for (int i = 0; i < 4; i++) {
        int row = ty * 4 + i;
        rv[row * 16 + tx] = bestv[i];
        ri[row * 16 + tx] = besti[i];
    }
    __syncthreads();
    if (tid < 64) {
        float bv = rv[tid * 16];
        int   bi = ri[tid * 16];
#pragma unroll
        for (int tt = 1; tt < 16; tt++) {
            float v = rv[tid * 16 + tt];
            int  ix = ri[tid * 16 + tt];
            if (v < bv || (v == bv && ix < bi)) { bv = v; bi = ix; }
        }
        g_nn[stage][m0 + tid] = bi;
    }
}

// ============================================================================
// Gather: zq = E[nn]; residual; nn as float; accumulate zq_sum; stage 3 forms
// straight-through decoder input. Stages 0-2 also compute the NEXT stage's
// ||ze_next||^2 with the exact sequential XLA chain.
// ============================================================================
__global__ void gather_kernel(const float* __restrict__ ze,
                              const float* __restrict__ E,
                              float* __restrict__ zq_out,
                              float* __restrict__ ze_next,   // null on stage 3
                              float* __restrict__ nn_f,
                              const float* __restrict__ ze1, // stage 3 only
                              int stage)
{
    __shared__ float buf[CDIM];
    int row = blockIdx.x;
    int c = threadIdx.x;
    int idx = g_nn[stage][row];
    float q = E[(size_t)idx * CDIM + c];
    size_t o = (size_t)row * CDIM + c;
    zq_out[o] = q;
    if (ze_next) {
        float zn = __fadd_rn(ze[o], -q);
        ze_next[o] = zn;
        buf[c] = zn;
    }
    float s = (stage == 0) ? q : __fadd_rn(g_zqsum[o], q);
    if (stage == 3) {
        float z1 = ze1[o];
        s = __fadd_rn(z1, __fadd_rn(s, -z1));   // ze1 + (zq_sum - ze1)
    }
    g_zqsum[o] = s;
    if (c == 0) nn_f[row] = (float)idx;

    if (ze_next) {
        __syncthreads();
        if (c == 0) {
            float acc = 0.f;
#pragma unroll 8
            for (int i = 0; i < CDIM; i++)
                acc = __fadd_rn(acc, __fmul_rn(buf[i], buf[i]));
            g_ze2[row] = acc;
        }
    }
}

// ============================================================================
// kernel_launch
// Output layout (float32): x_hat [N,768] | ze_1..4 [N,256] | zq_1..4 [N,256]
//                          | nn_1..4 [N]
// ============================================================================
extern "C" void kernel_launch(void* const* d_in, const int* in_sizes, int n_in,
                              void* d_out, int out_size)
{
    const float* x     = (const float*)d_in[0];
    const float* W_enc = (const float*)d_in[1];
    const float* b_enc = (const float*)d_in[2];
    const float* E[4]  = {(const float*)d_in[3], (const float*)d_in[4],
                          (const float*)d_in[5], (const float*)d_in[6]};
    const float* W_dec = (const float*)d_in[7];
    const float* b_dec = (const float*)d_in[8];

    float* out = (float*)d_out;

    const size_t NC      = (size_t)NROWS * CDIM;
    const size_t OFF_ZE  = (size_t)NROWS * INDIM;
    const size_t OFF_ZQ  = OFF_ZE + 4 * NC;
    const size_t OFF_NN  = OFF_ZQ + 4 * NC;

    float* xhat = out;
    const float* ze1 = out + OFF_ZE;

    void* zqsum_ptr = nullptr;
    cudaGetSymbolAddress(&zqsum_ptr, g_zqsum);

    cudaFuncSetAttribute(vq_argmin_kernel,
                         cudaFuncAttributeMaxDynamicSharedMemorySize, VQ_SMEM);

    // codebook norms (all 4 stages, one launch)
    esq4_kernel<<<(4 * KCODES) / 256, 256>>>(E[0], E[1], E[2], E[3]);

    // encoder: ze_1 = x @ W_enc + b_enc
    sgemm_bias_kernel<<<dim3(CDIM / 128, NROWS / 128), 256>>>(
        x, W_enc, b_enc, out + OFF_ZE, NROWS, INDIM, CDIM);

    // ||ze_1||^2 (later stages' norms are fused into gather)
    rownorm_kernel<<<NROWS / 256, 256>>>(out + OFF_ZE);

    // 4 sequential VQ stages
    for (int s = 0; s < 4; s++) {
        const float* zes = out + OFF_ZE + (size_t)s * NC;
        vq_argmin_kernel<<<NROWS / 64, 256, VQ_SMEM>>>(zes, E[s], s);
        float* zenext = (s < 3) ? (out + OFF_ZE + (size_t)(s + 1) * NC) : nullptr;
        gather_kernel<<<NROWS, 256>>>(zes, E[s],
                                      out + OFF_ZQ + (size_t)s * NC,
                                      zenext,
                                      out + OFF_NN + (size_t)s * NROWS,
                                      ze1, s);
    }

    // decoder: x_hat = decoder_input @ W_dec + b_dec
    sgemm_bias_kernel<<<dim3(INDIM / 128, NROWS / 128), 256>>>(
        (const float*)zqsum_ptr, W_dec, b_dec, xhat, NROWS, CDIM, INDIM);
}

// round 7
// speedup vs baseline: 1.2943x; 1.2943x over previous
#include <cuda_runtime.h>
#include <cstddef>
#include <cstdint>

#define NROWS 16384
#define INDIM 768
#define CDIM  256
#define KCODES 4096

// ---- device scratch (static: allowed; no runtime allocation) ----
__device__ float g_zqsum[NROWS * CDIM];      // running zq sum -> decoder input
__device__ float g_esq[4][KCODES];           // ||E_k||^2 per codebook
__device__ float g_ze2[NROWS];               // ||ze||^2 for current stage
__device__ int   g_nn[4][NROWS];             // argmin indices per stage
__device__ float g_ET[4][CDIM * KCODES];     // codebooks transposed [c][code]

// ---- packed f32x2 helpers: each lane rounds .rn independently, so each
// output keeps its single ascending-k fma chain -> bit-exact vs scalar ----
__device__ __forceinline__ void fma2(unsigned long long& d,
                                     unsigned long long a,
                                     unsigned long long b)
{
    asm("fma.rn.f32x2 %0, %1, %2, %0;" : "+l"(d) : "l"(a), "l"(b));
}
__device__ __forceinline__ unsigned long long dup2(float x)
{
    unsigned long long r;
    asm("mov.b64 %0, {%1, %1};" : "=l"(r) : "f"(x));
    return r;
}
__device__ __forceinline__ float2 unpk2(unsigned long long v)
{
    float2 r;
    asm("mov.b64 {%0, %1}, %2;" : "=f"(r.x), "=f"(r.y) : "l"(v));
    return r;
}
__device__ __forceinline__ void cp_async16(uint32_t dst_smem, const void* src)
{
    asm volatile("cp.async.cg.shared.global [%0], [%1], 16;"
                 :: "r"(dst_smem), "l"(src) : "memory");
}

// ============================================================================
// fp32 SGEMM with bias via packed f32x2: C = A @ B + bias.
// 128x128 tile, 8x8 per thread (4 f32x2 column-pairs).
// ============================================================================
__global__ __launch_bounds__(256) void sgemm_bias_kernel(
    const float* __restrict__ A, const float* __restrict__ B,
    const float* __restrict__ bias, float* __restrict__ C,
    int M, int Kd, int Nn)
{
    __shared__ __align__(16) float As[32][132];  // [kk][mm]
    __shared__ __align__(16) float Bs[32][132];  // [kk][nn]

    const int tid = threadIdx.x;
    const int tx = tid & 15;
    const int ty = tid >> 4;
    const int m0 = blockIdx.y * 128;
    const int n0 = blockIdx.x * 128;

    unsigned long long acc[8][4];
#pragma unroll
    for (int i = 0; i < 8; i++)
#pragma unroll
        for (int j = 0; j < 4; j++) acc[i][j] = 0ull;

    for (int k0 = 0; k0 < Kd; k0 += 32) {
#pragma unroll
        for (int i = 0; i < 16; i++) {
            int idx = tid + i * 256;
            int mm = idx >> 5, kk = idx & 31;
            As[kk][mm] = A[(size_t)(m0 + mm) * Kd + (k0 + kk)];
        }
#pragma unroll
        for (int i = 0; i < 16; i++) {
            int idx = tid + i * 256;
            int kk = idx >> 7, nn = idx & 127;
            Bs[kk][nn] = B[(size_t)(k0 + kk) * Nn + (n0 + nn)];
        }
        __syncthreads();

#pragma unroll
        for (int kk = 0; kk < 32; kk++) {
            float4 a0 = *(const float4*)&As[kk][ty * 4];
            float4 a1 = *(const float4*)&As[kk][64 + ty * 4];
            unsigned long long aa[8] = {dup2(a0.x), dup2(a0.y), dup2(a0.z), dup2(a0.w),
                                        dup2(a1.x), dup2(a1.y), dup2(a1.z), dup2(a1.w)};
            ulonglong2 b0 = *(const ulonglong2*)&Bs[kk][tx * 4];
            ulonglong2 b1 = *(const ulonglong2*)&Bs[kk][64 + tx * 4];
            unsigned long long bb[4] = {b0.x, b0.y, b1.x, b1.y};
#pragma unroll
            for (int i = 0; i < 8; i++)
#pragma unroll
                for (int j = 0; j < 4; j++)
                    fma2(acc[i][j], aa[i], bb[j]);
        }
        __syncthreads();
    }

#pragma unroll
    for (int i = 0; i < 8; i++) {
        int row = m0 + ((i < 4) ? (ty * 4 + i) : (64 + ty * 4 + (i - 4)));
#pragma unroll
        for (int jh = 0; jh < 2; jh++) {
            int col = n0 + (jh ? (64 + tx * 4) : (tx * 4));
            float2 p0 = unpk2(acc[i][jh * 2 + 0]);
            float2 p1 = unpk2(acc[i][jh * 2 + 1]);
            float4 v;
            v.x = __fadd_rn(p0.x, bias[col + 0]);
            v.y = __fadd_rn(p0.y, bias[col + 1]);
            v.z = __fadd_rn(p1.x, bias[col + 2]);
            v.w = __fadd_rn(p1.y, bias[col + 3]);
            *(float4*)&C[(size_t)row * Nn + col] = v;
        }
    }
}

// ============================================================================
// Tiled transpose of all 4 codebooks: E[code][c] -> g_ET[stage][c][code].
// grid (KCODES/32, CDIM/32, 4), block (32, 8).
// ============================================================================
__global__ void transpose4_kernel(const float* __restrict__ E0,
                                  const float* __restrict__ E1,
                                  const float* __restrict__ E2,
                                  const float* __restrict__ E3)
{
    __shared__ float tile[32][33];
    int stage = blockIdx.z;
    const float* E = (stage == 0) ? E0 : (stage == 1) ? E1 : (stage == 2) ? E2 : E3;
    int code0 = blockIdx.x * 32;
    int c0 = blockIdx.y * 32;
    int txx = threadIdx.x, tyy = threadIdx.y;
#pragma unroll
    for (int r = 0; r < 4; r++) {
        int row = tyy + r * 8;
        tile[row][txx] = E[(size_t)(code0 + row) * CDIM + (c0 + txx)];
    }
    __syncthreads();
    float* ET = g_ET[stage];
#pragma unroll
    for (int r = 0; r < 4; r++) {
        int row = tyy + r * 8;
        ET[(size_t)(c0 + row) * KCODES + (code0 + txx)] = tile[txx][row];
    }
}

// ============================================================================
// ||E_k||^2 for ALL FOUR codebooks in one launch (XLA rounding order).
// ============================================================================
__global__ void esq4_kernel(const float* __restrict__ E0,
                            const float* __restrict__ E1,
                            const float* __restrict__ E2,
                            const float* __restrict__ E3)
{
    int gid = blockIdx.x * 256 + threadIdx.x;
    int stage = gid >> 12;
    int row = gid & (KCODES - 1);
    const float* E = (stage == 0) ? E0 : (stage == 1) ? E1 : (stage == 2) ? E2 : E3;
    const float* e = E + (size_t)row * CDIM;
    float s = 0.f;
#pragma unroll 8
    for (int c = 0; c < CDIM; c++) {
        float v = e[c];
        s = __fadd_rn(s, __fmul_rn(v, v));
    }
    g_esq[stage][row] = s;
}

// ============================================================================
// ||ze||^2 per row (stage 0 only; later stages fused into gather).
// ============================================================================
__global__ void rownorm_kernel(const float* __restrict__ ze)
{
    int row = blockIdx.x * 256 + threadIdx.x;
    if (row >= NROWS) return;
    const float* p = ze + (size_t)row * CDIM;
    float s = 0.f;
#pragma unroll 8
    for (int c = 0; c < CDIM; c++) {
        float v = __ldg(p + c);
        s = __fadd_rn(s, __fmul_rn(v, v));
    }
    g_ze2[row] = s;
}

// ============================================================================
// Fused score-GEMM + argmin, packed f32x2, 512 threads.
// BM=128 rows x BN=256 codes per chunk, BK=32, 8x8 per thread.
// Persistent ze tile (filled once); E tiles streamed from the pre-transposed
// g_ET via double-buffered cp.async (copy of chunk t+1 overlaps compute of t).
// d_k = fl( fl( Z - fl(2*s_k) ) + esq_k ); single fma chain per score;
// tie-break lowest index.
// Dynamic smem: As 256x132 | Bs 2 x 32x264  = 202,752 B. 1 CTA/SM, 16 warps.
// ============================================================================
#define ASTRIDE 132
#define BSTRIDE 264
#define VQ_SMEM ((256 * ASTRIDE + 2 * 32 * BSTRIDE) * 4)

__global__ __launch_bounds__(512, 1) void vq_argmin_kernel(
    const float* __restrict__ ze,   // NROWS x CDIM
    int stage)
{
    extern __shared__ __align__(16) float sm[];
    float* As = sm;                         // [256 c][ASTRIDE]  persistent
    float* Bs = sm + 256 * ASTRIDE;         // [2][32 kk][BSTRIDE]

    const int tid = threadIdx.x;
    const int tx = tid & 31;                // code group 0..31
    const int ty = tid >> 5;                // row group  0..15
    const int m0 = blockIdx.x * 128;
    const float* __restrict__ esq = g_esq[stage];
    const float* __restrict__ ET = g_ET[stage];

    const uint32_t bs_u32 =
        (uint32_t)__cvta_generic_to_shared(Bs);

    // ---- kick off async copy of chunk 0 (cb=0, c0=0) ----
#pragma unroll
    for (int i = 0; i < 4; i++) {
        int idx = tid + i * 512;            // 0..2047 float4 units
        int kk = idx >> 6, c4 = idx & 63;
        cp_async16(bs_u32 + (uint32_t)(kk * BSTRIDE + c4 * 4) * 4,
                   ET + (size_t)kk * KCODES + c4 * 4);
    }
    asm volatile("cp.async.commit_group;" ::: "memory");

    // ---- one-time fill of the ze tile (128 rows x 256 c), coalesced ----
#pragma unroll 8
    for (int i = 0; i < 64; i++) {
        int idx = tid + i * 512;
        int c = idx & 255, mm = idx >> 8;
        As[c * ASTRIDE + mm] = ze[(size_t)(m0 + mm) * CDIM + c];
    }

    float zrow[8];
#pragma unroll
    for (int i = 0; i < 8; i++) {
        int row = (i < 4) ? (ty * 4 + i) : (64 + ty * 4 + (i - 4));
        zrow[i] = g_ze2[m0 + row];
    }

    float bestv[8];
    int   besti[8];
#pragma unroll
    for (int i = 0; i < 8; i++) { bestv[i] = 3.4e38f; besti[i] = 0; }

    unsigned long long acc[8][4];

    // 128 chunks: t -> cb = (t>>3)*256, c0 = (t&7)*32
    for (int t = 0; t < 128; t++) {
        asm volatile("cp.async.wait_group 0;" ::: "memory");
        __syncthreads();   // chunk t resident; everyone done with buf (t+1)&1

        // launch async copy of chunk t+1 into the other buffer
        if (t < 127) {
            const int t1 = t + 1;
            const int cb1 = (t1 >> 3) * 256;
            const int c01 = (t1 & 7) * 32;
            const uint32_t dstb = bs_u32 +
                (uint32_t)((t1 & 1) * 32 * BSTRIDE) * 4;
#pragma unroll
            for (int i = 0; i < 4; i++) {
                int idx = tid + i * 512;
                int kk = idx >> 6, c4 = idx & 63;
                cp_async16(dstb + (uint32_t)(kk * BSTRIDE + c4 * 4) * 4,
                           ET + (size_t)(c01 + kk) * KCODES + cb1 + c4 * 4);
            }
            asm volatile("cp.async.commit_group;" ::: "memory");
        }

        const int cb = (t >> 3) * 256;
        const int c0 = (t & 7) * 32;

        if ((t & 7) == 0) {
#pragma unroll
            for (int i = 0; i < 8; i++)
#pragma unroll
                for (int j = 0; j < 4; j++) acc[i][j] = 0ull;
        }

        const float* Bp = Bs + (t & 1) * (32 * BSTRIDE);
#pragma unroll
        for (int kk = 0; kk < 32; kk++) {
            const float* ar = As + (c0 + kk) * ASTRIDE;
            const float* br = Bp + kk * BSTRIDE;
            float4 a0 = *(const float4*)&ar[ty * 4];          // broadcast
            float4 a1 = *(const float4*)&ar[64 + ty * 4];     // broadcast
            unsigned long long aa[8] = {dup2(a0.x), dup2(a0.y), dup2(a0.z), dup2(a0.w),
                                        dup2(a1.x), dup2(a1.y), dup2(a1.z), dup2(a1.w)};
            ulonglong2 b0 = *(const ulonglong2*)&br[tx * 4];
            ulonglong2 b1 = *(const ulonglong2*)&br[128 + tx * 4];
            unsigned long long bb[4] = {b0.x, b0.y, b1.x, b1.y};
#pragma unroll
            for (int i = 0; i < 8; i++)
#pragma unroll
                for (int j = 0; j < 4; j++)
                    fma2(acc[i][j], aa[i], bb[j]);
        }

        // end of a cb group: argmin update  d = fl( fl(Z - fl(2*s)) + esq )
        if ((t & 7) == 7) {
#pragma unroll
            for (int half = 0; half < 2; half++) {
#pragma unroll
                for (int h = 0; h < 2; h++) {
                    int j2 = half * 2 + h;
                    int col = cb + half * 128 + tx * 4 + h * 2;
                    float eq0 = esq[col];
                    float eq1 = esq[col + 1];
#pragma unroll
                    for (int i = 0; i < 8; i++) {
                        float2 pv = unpk2(acc[i][j2]);
                        float t0 = __fmul_rn(2.0f, pv.x);
                        float v0 = __fadd_rn(__fadd_rn(zrow[i], -t0), eq0);
                        if (v0 < bestv[i]) { bestv[i] = v0; besti[i] = col; }
                        float t1v = __fmul_rn(2.0f, pv.y);
                        float v1 = __fadd_rn(__fadd_rn(zrow[i], -t1v), eq1);
                        if (v1 < bestv[i]) { bestv[i] = v1; besti[i] = col + 1; }
                    }
                }
            }
        }
    }

    // cross-thread reduction over the 32 tx lanes sharing each row
    __syncthreads();
    float* rv = sm;                    // 128*32 floats
    int*   ri = (int*)(sm + 4096);     // 128*32 ints
#pragma unroll
    for (int i = 0; i < 8; i++) {
        int row = (i < 4) ? (ty * 4 + i) : (64 + ty * 4 + (i - 4));
        rv[row * 32 + tx] = bestv[i];
        ri[row * 32 + tx] = besti[i];
    }
    __syncthreads();
    if (tid < 128) {
        float bv = rv[tid * 32];
        int   bi = ri[tid * 32];
#pragma unroll
        for (int tt = 1; tt < 32; tt++) {
            float v = rv[tid * 32 + tt];
            int  ix = ri[tid * 32 + tt];
            if (v < bv || (v == bv && ix < bi)) { bv = v; bi = ix; }
        }
        g_nn[stage][m0 + tid] = bi;
    }
}

// ============================================================================
// Gather: zq = E[nn]; residual; nn as float; accumulate zq_sum; stage 3 forms
// straight-through decoder input. Stages 0-2 also compute the NEXT stage's
// ||ze_next||^2 with the exact sequential XLA chain.
// ============================================================================
__global__ void gather_kernel(const float* __restrict__ ze,
                              const float* __restrict__ E,
                              float* __restrict__ zq_out,
                              float* __restrict__ ze_next,   // null on stage 3
                              float* __restrict__ nn_f,
                              const float* __restrict__ ze1, // stage 3 only
                              int stage)
{
    __shared__ float buf[CDIM];
    int row = blockIdx.x;
    int c = threadIdx.x;
    int idx = g_nn[stage][row];
    float q = E[(size_t)idx * CDIM + c];
    size_t o = (size_t)row * CDIM + c;
    zq_out[o] = q;
    if (ze_next) {
        float zn = __fadd_rn(ze[o], -q);
        ze_next[o] = zn;
        buf[c] = zn;
    }
    float s = (stage == 0) ? q : __fadd_rn(g_zqsum[o], q);
    if (stage == 3) {
        float z1 = ze1[o];
        s = __fadd_rn(z1, __fadd_rn(s, -z1));   // ze1 + (zq_sum - ze1)
    }
    g_zqsum[o] = s;
    if (c == 0) nn_f[row] = (float)idx;

    if (ze_next) {
        __syncthreads();
        if (c == 0) {
            float acc = 0.f;
#pragma unroll 8
            for (int i = 0; i < CDIM; i++)
                acc = __fadd_rn(acc, __fmul_rn(buf[i], buf[i]));
            g_ze2[row] = acc;
        }
    }
}

// ============================================================================
// kernel_launch
// Output layout (float32): x_hat [N,768] | ze_1..4 [N,256] | zq_1..4 [N,256]
//                          | nn_1..4 [N]
// ============================================================================
extern "C" void kernel_launch(void* const* d_in, const int* in_sizes, int n_in,
                              void* d_out, int out_size)
{
    const float* x     = (const float*)d_in[0];
    const float* W_enc = (const float*)d_in[1];
    const float* b_enc = (const float*)d_in[2];
    const float* E[4]  = {(const float*)d_in[3], (const float*)d_in[4],
                          (const float*)d_in[5], (const float*)d_in[6]};
    const float* W_dec = (const float*)d_in[7];
    const float* b_dec = (const float*)d_in[8];

    float* out = (float*)d_out;

    const size_t NC      = (size_t)NROWS * CDIM;
    const size_t OFF_ZE  = (size_t)NROWS * INDIM;
    const size_t OFF_ZQ  = OFF_ZE + 4 * NC;
    const size_t OFF_NN  = OFF_ZQ + 4 * NC;

    float* xhat = out;
    const float* ze1 = out + OFF_ZE;

    void* zqsum_ptr = nullptr;
    cudaGetSymbolAddress(&zqsum_ptr, g_zqsum);

    cudaFuncSetAttribute(vq_argmin_kernel,
                         cudaFuncAttributeMaxDynamicSharedMemorySize, VQ_SMEM);

    // codebook preprocessing: norms + transposes (one-time, overlapping)
    esq4_kernel<<<(4 * KCODES) / 256, 256>>>(E[0], E[1], E[2], E[3]);
    transpose4_kernel<<<dim3(KCODES / 32, CDIM / 32, 4), dim3(32, 8)>>>(
        E[0], E[1], E[2], E[3]);

    // encoder: ze_1 = x @ W_enc + b_enc
    sgemm_bias_kernel<<<dim3(CDIM / 128, NROWS / 128), 256>>>(
        x, W_enc, b_enc, out + OFF_ZE, NROWS, INDIM, CDIM);

    // ||ze_1||^2 (later stages' norms are fused into gather)
    rownorm_kernel<<<NROWS / 256, 256>>>(out + OFF_ZE);

    // 4 sequential VQ stages
    for (int s = 0; s < 4; s++) {
        const float* zes = out + OFF_ZE + (size_t)s * NC;
        vq_argmin_kernel<<<NROWS / 128, 512, VQ_SMEM>>>(zes, s);
        float* zenext = (s < 3) ? (out + OFF_ZE + (size_t)(s + 1) * NC) : nullptr;
        gather_kernel<<<NROWS, 256>>>(zes, E[s],
                                      out + OFF_ZQ + (size_t)s * NC,
                                      zenext,
                                      out + OFF_NN + (size_t)s * NROWS,
                                      ze1, s);
    }

    // decoder: x_hat = decoder_input @ W_dec + b_dec
    sgemm_bias_kernel<<<dim3(INDIM / 128, NROWS / 128), 256>>>(
        (const float*)zqsum_ptr, W_dec, b_dec, xhat, NROWS, CDIM, INDIM);
}